// round 16
// baseline (speedup 1.0000x reference)
#include <cuda_runtime.h>
#include <cuda_fp16.h>
#include <stdint.h>
#include <math.h>

// ---------------- problem constants ----------------
#define BATCH 2
#define SEQ   1024
#define HDIM  2048
#define NH    16
#define NKV   4
#define HD    128
#define NEXP  8
#define IDIM  2048
#define TTOK  (BATCH*SEQ)          // 2048 tokens
#define QKVW  ((NH+2*NKV)*HD)      // 3072
#define SCALE 0.08838834764831845f // 128^-0.5
#define EPS_RMS 1e-5f
#define EPS_L2  1e-6f

// ---------------- scratch (device globals; no allocation allowed) ----------
__device__ float  g_qkv [TTOK*QKVW];
__device__ float  g_x2  [TTOK*HDIM];
__device__ float  g_h2  [TTOK*HDIM];
__device__ float  g_gus [TTOK*2*IDIM];
__device__ float  g_gur [TTOK*2*IDIM];

__device__ __half g_h16  [TTOK*HDIM];
__device__ __half g_q16  [TTOK*NH*HD];
__device__ __half g_k16  [TTOK*NKV*HD];
__device__ __half g_o16  [TTOK*NH*HD];
__device__ __half g_h2_16[TTOK*HDIM];
__device__ __half g_acs16[TTOK*IDIM];
__device__ __half g_acr16[TTOK*IDIM];

// fp16 weights, SAME [K][N] layout as fp32 originals (no transpose)
__device__ __half g_wqkv16 [HDIM*QKVW];
__device__ __half g_wo16   [NH*HD*HDIM];
__device__ __half g_wshgu16[HDIM*2*IDIM];
__device__ __half g_wshdn16[IDIM*HDIM];
__device__ __half g_wgu16  [(size_t)NEXP*HDIM*2*IDIM];
__device__ __half g_wdn16  [(size_t)NEXP*IDIM*HDIM];

__device__ int   g_cnt[NEXP];
__device__ int   g_off[NEXP];
__device__ int   g_tok_expert[TTOK];
__device__ int   g_tok_rank[TTOK];
__device__ float g_tok_scale[TTOK];
__device__ int   g_slot_tok[TTOK];

// ---------------- common PTX helpers ----------------
__device__ __forceinline__ void cp16(uint32_t dst, const void* src) {
    asm volatile("cp.async.ca.shared.global [%0], [%1], 16;" :: "r"(dst), "l"(src));
}
__device__ __forceinline__ uint32_t f2tf32(float f) {
    uint32_t u;
    asm("cvt.rna.tf32.f32 %0, %1;" : "=r"(u) : "f"(f));
    return u;
}
__device__ __forceinline__ void mma_tf32(float* c, const uint32_t* a, const uint32_t* b) {
    asm volatile(
        "mma.sync.aligned.m16n8k8.row.col.f32.tf32.tf32.f32 "
        "{%0,%1,%2,%3}, {%4,%5,%6,%7}, {%8,%9}, {%0,%1,%2,%3};"
        : "+f"(c[0]), "+f"(c[1]), "+f"(c[2]), "+f"(c[3])
        : "r"(a[0]), "r"(a[1]), "r"(a[2]), "r"(a[3]), "r"(b[0]), "r"(b[1]));
}
__device__ __forceinline__ void mma_f16(float* c, const uint32_t* a, const uint32_t* b) {
    asm volatile(
        "mma.sync.aligned.m16n8k16.row.col.f32.f16.f16.f32 "
        "{%0,%1,%2,%3}, {%4,%5,%6,%7}, {%8,%9}, {%0,%1,%2,%3};"
        : "+f"(c[0]), "+f"(c[1]), "+f"(c[2]), "+f"(c[3])
        : "r"(a[0]), "r"(a[1]), "r"(a[2]), "r"(a[3]), "r"(b[0]), "r"(b[1]));
}
__device__ __forceinline__ void ldsm_x4(uint32_t& r0, uint32_t& r1, uint32_t& r2, uint32_t& r3,
                                        uint32_t addr) {
    asm volatile("ldmatrix.sync.aligned.m8n8.x4.shared.b16 {%0,%1,%2,%3}, [%4];"
                 : "=r"(r0), "=r"(r1), "=r"(r2), "=r"(r3) : "r"(addr));
}
__device__ __forceinline__ void ldsm_x4_t(uint32_t& r0, uint32_t& r1, uint32_t& r2, uint32_t& r3,
                                          uint32_t addr) {
    asm volatile("ldmatrix.sync.aligned.m8n8.x4.trans.shared.b16 {%0,%1,%2,%3}, [%4];"
                 : "=r"(r0), "=r"(r1), "=r"(r2), "=r"(r3) : "r"(addr));
}

// ---------------- layout-preserving fp32 -> fp16 convert (R11 proven) ----
__global__ __launch_bounds__(256)
void cvt_kernel(const float* __restrict__ in, __half* __restrict__ out, size_t n)
{
    size_t i = ((size_t)blockIdx.x * 256 + threadIdx.x) * 8;
    if (i >= n) return;
    float4 v0 = *(const float4*)(in + i);
    float4 v1 = *(const float4*)(in + i + 4);
    __half2 h0 = __floats2half2_rn(v0.x, v0.y);
    __half2 h1 = __floats2half2_rn(v0.z, v0.w);
    __half2 h2 = __floats2half2_rn(v1.x, v1.y);
    __half2 h3 = __floats2half2_rn(v1.z, v1.w);
    uint4 pack;
    pack.x = *(uint32_t*)&h0; pack.y = *(uint32_t*)&h1;
    pack.z = *(uint32_t*)&h2; pack.w = *(uint32_t*)&h3;
    *(uint4*)(out + i) = pack;
}

// ---------------- RMSNorm (fp16 out, optional fp32 out) ----------------
__global__ void rmsnorm_kernel(const float* __restrict__ x,
                               const float* __restrict__ w,
                               __half* __restrict__ out16,
                               float* __restrict__ out32)
{
    int t = blockIdx.x;
    const float* xr = x + (size_t)t * HDIM;
    float ss = 0.f;
    for (int i = threadIdx.x; i < HDIM; i += blockDim.x) {
        float v = xr[i];
        ss += v * v;
    }
    __shared__ float red[8];
    int lane = threadIdx.x & 31, wid = threadIdx.x >> 5;
    #pragma unroll
    for (int o = 16; o; o >>= 1) ss += __shfl_xor_sync(0xffffffffu, ss, o);
    if (lane == 0) red[wid] = ss;
    __syncthreads();
    if (wid == 0) {
        float v = (lane < (blockDim.x >> 5)) ? red[lane] : 0.f;
        #pragma unroll
        for (int o = 16; o; o >>= 1) v += __shfl_xor_sync(0xffffffffu, v, o);
        if (lane == 0) red[0] = v;
    }
    __syncthreads();
    float r = rsqrtf(red[0] / (float)HDIM + EPS_RMS);
    for (int i = threadIdx.x; i < HDIM; i += blockDim.x) {
        float v = xr[i] * r * w[i];
        out16[(size_t)t * HDIM + i] = __float2half(v);
        if (out32) out32[(size_t)t * HDIM + i] = v;
    }
}

// =====================================================================
// fp16 tensor-core GEMM: C[M,N] = A[M,K] @ B[K,N]  (+D)
// A fp16 [M][K] (ldmatrix.x4); B fp16 [K][N] (ldmatrix.x4.trans)
// CTA 256x128 (256 thr, 8 warps = 4m x 2n, warp tile 64x64),
// K-tile 32, double-buffered cp.async. Halves B L2 re-reads vs 128x128.
// modes: 0 plain(+D), 1 expert gate_up (gather+scale), 2 expert down (scatter)
// =====================================================================
#define AHS 40     // A smem stride (halves)
#define BHS 136    // B smem stride (halves)
#define A_BUF   (256*AHS*2)     // 20480
#define BH_BUF  (32*BHS*2)      // 8704
#define B_OFF   (2*A_BUF)       // 40960
#define HG_SMEM (B_OFF + 2*BH_BUF)  // 58368

__global__ __launch_bounds__(256)
void hgemm(int M, int N, int K,
           const __half* __restrict__ A,
           const __half* __restrict__ B, size_t b_expert_stride,
           float* __restrict__ C,
           const float* __restrict__ D,
           int mode)
{
    extern __shared__ char sm[];
    uint32_t smBase = (uint32_t)__cvta_generic_to_shared(sm);

    int crow = blockIdx.y * 256;
    int ccol = blockIdx.x * 128;
    int cnt = M, off = 0;
    if (mode) {
        int e = blockIdx.z;
        cnt = g_cnt[e];
        off = g_off[e];
        B += (size_t)e * b_expert_stride;
        if (crow >= cnt) return;
    }

    const int tid = threadIdx.x;
    const int warp = tid >> 5, lane = tid & 31;
    const int g = lane >> 2, tig = lane & 3;
    const int wm = (warp >> 1) * 64;     // 4 m-warps
    const int wn = (warp & 1) * 64;      // 2 n-warps

    // ---- A staging: 256 rows x 4 chunks(16B) = 1024 chunks -> 4/thread ----
    const __half* a_src[4];
    uint32_t a_off_s[4];
    #pragma unroll
    for (int i = 0; i < 4; i++) {
        int idx = tid + i * 256;
        int r = idx >> 2, c8 = (idx & 3) * 8;
        int gr = crow + r;
        int arow;
        if (mode == 1)      arow = g_slot_tok[off + (gr < cnt ? gr : cnt - 1)];
        else if (mode == 2) arow = off + (gr < cnt ? gr : cnt - 1);
        else                arow = (gr < M ? gr : M - 1);
        a_src[i] = A + (size_t)arow * K + c8;
        a_off_s[i] = (uint32_t)((r * AHS + c8) * 2);
    }
    // ---- B staging: 32 rows x 128 halves = 512 chunks -> 2/thread ----
    const __half* b_src[2];
    uint32_t b_off_s[2];
    #pragma unroll
    for (int i = 0; i < 2; i++) {
        int idx = tid + i * 256;
        int r = idx >> 4, c8 = (idx & 15) * 8;
        b_src[i] = B + (size_t)r * N + ccol + c8;
        b_off_s[i] = (uint32_t)((r * BHS + c8) * 2);
    }

    // ldmatrix per-lane offsets
    int lr8 = lane & 7, seg1 = (lane >> 3) & 1, seg2 = lane >> 4;
    uint32_t a_frag = (uint32_t)(((wm + lr8 + seg1 * 8) * AHS + seg2 * 8) * 2);
    int bk = lane & 15, bn = (lane >> 4) * 8;   // trans frag: k row, n half

    float acc[4][8][4];
    #pragma unroll
    for (int mt = 0; mt < 4; mt++)
        #pragma unroll
        for (int nt = 0; nt < 8; nt++)
            #pragma unroll
            for (int r = 0; r < 4; r++) acc[mt][nt][r] = 0.f;

    const int KT = K / 32;

    // prefetch stage 0
    #pragma unroll
    for (int i = 0; i < 4; i++) cp16(smBase + a_off_s[i], a_src[i]);
    #pragma unroll
    for (int i = 0; i < 2; i++) cp16(smBase + B_OFF + b_off_s[i], b_src[i]);
    asm volatile("cp.async.commit_group;");

    for (int kt = 0; kt < KT; kt++) {
        int buf = kt & 1;
        if (kt + 1 < KT) {
            int k0 = (kt + 1) * 32;
            int nbuf = buf ^ 1;
            #pragma unroll
            for (int i = 0; i < 4; i++)
                cp16(smBase + nbuf * A_BUF + a_off_s[i], a_src[i] + k0);
            #pragma unroll
            for (int i = 0; i < 2; i++)
                cp16(smBase + B_OFF + nbuf * BH_BUF + b_off_s[i], b_src[i] + (size_t)k0 * N);
            asm volatile("cp.async.commit_group;");
            asm volatile("cp.async.wait_group 1;");
        } else {
            asm volatile("cp.async.wait_group 0;");
        }
        __syncthreads();

        uint32_t aB  = smBase + buf * A_BUF + a_frag;
        uint32_t bhB = smBase + B_OFF + buf * BH_BUF;

        uint32_t ua[2][4][4], ub[2][8][2];
        #pragma unroll
        for (int ks = 0; ks < 2; ks++) {
            uint32_t ka = aB + ks * 32;
            #pragma unroll
            for (int mt = 0; mt < 4; mt++)
                ldsm_x4(ua[ks][mt][0], ua[ks][mt][1], ua[ks][mt][2], ua[ks][mt][3],
                        ka + mt * (16 * AHS * 2));
            #pragma unroll
            for (int j = 0; j < 4; j++) {
                uint32_t addr = bhB + (uint32_t)(((ks * 16 + bk) * BHS + wn + bn + j * 16) * 2);
                ldsm_x4_t(ub[ks][2*j][0], ub[ks][2*j][1], ub[ks][2*j+1][0], ub[ks][2*j+1][1],
                          addr);
            }
        }
        #pragma unroll
        for (int ks = 0; ks < 2; ks++)
            #pragma unroll
            for (int mt = 0; mt < 4; mt++)
                #pragma unroll
                for (int nt = 0; nt < 8; nt++)
                    mma_f16(acc[mt][nt], ua[ks][mt], ub[ks][nt]);
        __syncthreads();
    }

    // ---------------- epilogue ----------------
    #pragma unroll
    for (int mt = 0; mt < 4; mt++) {
        #pragma unroll
        for (int h = 0; h < 2; h++) {
            int rl = wm + mt * 16 + g + h * 8;
            int gr = crow + rl;
            if (mode == 0) {
                if (gr < M) {
                    size_t rbase = (size_t)gr * N;
                    #pragma unroll
                    for (int nt = 0; nt < 8; nt++) {
                        int c = ccol + wn + nt * 8 + tig * 2;
                        float v0 = acc[mt][nt][h * 2 + 0];
                        float v1 = acc[mt][nt][h * 2 + 1];
                        if (D) {
                            float2 dv = *(const float2*)(D + rbase + c);
                            v0 += dv.x; v1 += dv.y;
                        }
                        *(float2*)(C + rbase + c) = make_float2(v0, v1);
                    }
                }
            } else if (mode == 1) {
                if (gr < cnt) {
                    int slot = off + gr;
                    float s = g_tok_scale[g_slot_tok[slot]];
                    size_t rbase = (size_t)slot * N;
                    #pragma unroll
                    for (int nt = 0; nt < 8; nt++) {
                        int c = ccol + wn + nt * 8 + tig * 2;
                        *(float2*)(C + rbase + c) =
                            make_float2(s * acc[mt][nt][h * 2 + 0],
                                        s * acc[mt][nt][h * 2 + 1]);
                    }
                }
            } else {
                if (gr < cnt) {
                    int tok = g_slot_tok[off + gr];
                    size_t rbase = (size_t)tok * N;
                    #pragma unroll
                    for (int nt = 0; nt < 8; nt++) {
                        int c = ccol + wn + nt * 8 + tig * 2;
                        float2* cp = (float2*)(C + rbase + c);
                        float2 cv = *cp;
                        cv.x += acc[mt][nt][h * 2 + 0];
                        cv.y += acc[mt][nt][h * 2 + 1];
                        *cp = cv;
                    }
                }
            }
        }
    }
}

// ---------------- RoPE + L2-norm for q & k -> fp16 ----------------
__global__ void rope_l2_kernel(const float* __restrict__ qkv,
                               const float* __restrict__ freqs,
                               __half* __restrict__ qout,
                               __half* __restrict__ kout)
{
    int t = blockIdx.x;
    int lane = threadIdx.x & 31, w = threadIdx.x >> 5;
    int hh = blockIdx.y * 4 + w;
    int s = t & (SEQ - 1);

    const float* src;
    __half* dst;
    if (hh < NH) {
        src = qkv + (size_t)t * QKVW + hh * HD;
        dst = qout + (size_t)t * NH * HD + hh * HD;
    } else {
        int kv = hh - NH;
        src = qkv + (size_t)t * QKVW + NH * HD + kv * HD;
        dst = kout + (size_t)t * NKV * HD + kv * HD;
    }
    float4 xv = *(const float4*)(src + lane * 4);
    float4 fv = *(const float4*)(freqs + (size_t)s * HD + lane * 4);
    float o0 = xv.x * fv.x - xv.y * fv.y;
    float o1 = xv.x * fv.y + xv.y * fv.x;
    float o2 = xv.z * fv.z - xv.w * fv.w;
    float o3 = xv.z * fv.w + xv.w * fv.z;
    float ss = o0*o0 + o1*o1 + o2*o2 + o3*o3;
    #pragma unroll
    for (int o = 16; o; o >>= 1) ss += __shfl_xor_sync(0xffffffffu, ss, o);
    float r = rsqrtf(ss / (float)HD + EPS_L2);
    __half2 p0 = __floats2half2_rn(o0 * r, o1 * r);
    __half2 p1 = __floats2half2_rn(o2 * r, o3 * r);
    *(__half2*)(dst + lane * 4)     = p0;
    *(__half2*)(dst + lane * 4 + 2) = p1;
}

// =====================================================================
// flash attention (R11 proven): fp16 S-path, tf32 P@V, 64 q rows/block,
// longest q-tiles first.
// =====================================================================
#define KH_STRIDE 136   // halves
#define VS_STRIDE 136   // floats
#define P_STRIDE  68    // floats
#define FA_SMEM   (64*KH_STRIDE*2 + 64*VS_STRIDE*4 + 64*P_STRIDE*4)

__global__ __launch_bounds__(128)
void flash_attn_kernel(const __half* __restrict__ q,
                       const __half* __restrict__ k,
                       const float* __restrict__ qkv,
                       __half* __restrict__ o)
{
    extern __shared__ char fsm[];
    __half* Ks = (__half*)fsm;                         // [64][KH_STRIDE]
    float*  Vs = (float*)(fsm + 64 * KH_STRIDE * 2);   // [64][VS_STRIDE]
    float*  Ps = Vs + 64 * VS_STRIDE;                  // [64][P_STRIDE]

    int bh = blockIdx.x;
    int b = bh >> 4, h = bh & 15;
    int kvh = h >> 2;
    int qt = gridDim.y - 1 - blockIdx.y;   // longest first
    int q0 = qt * 64;

    int tid = threadIdx.x, warp = tid >> 5, lane = tid & 31;
    int g = lane >> 2, tig = lane & 3;

    int qr0 = q0 + warp * 16 + g;
    int qr1 = qr0 + 8;
    const __half* qb0 = q + ((size_t)(b * SEQ + qr0) * NH + h) * HD;
    const __half* qb1 = q + ((size_t)(b * SEQ + qr1) * NH + h) * HD;
    uint32_t qa[8][4];
    #pragma unroll
    for (int ks = 0; ks < 8; ks++) {
        int c = ks * 16 + tig * 2;
        qa[ks][0] = *(const uint32_t*)&qb0[c];
        qa[ks][1] = *(const uint32_t*)&qb1[c];
        qa[ks][2] = *(const uint32_t*)&qb0[c + 8];
        qa[ks][3] = *(const uint32_t*)&qb1[c + 8];
    }

    float oacc[16][4];
    #pragma unroll
    for (int dt = 0; dt < 16; dt++)
        #pragma unroll
        for (int r = 0; r < 4; r++) oacc[dt][r] = 0.f;
    float m0 = -1e30f, m1 = -1e30f, l0 = 0.f, l1 = 0.f;

    uint32_t ksb = (uint32_t)__cvta_generic_to_shared(Ks);
    uint32_t vsb = (uint32_t)__cvta_generic_to_shared(Vs);

    const int ktiles = qt + 1;
    for (int kt = 0; kt < ktiles; kt++) {
        const __half* kptr = k + ((size_t)(b * SEQ + kt * 64) * NKV + kvh) * HD;
        const float*  vptr = qkv + (size_t)(b * SEQ + kt * 64) * QKVW + (NH + NKV) * HD + kvh * HD;
        #pragma unroll
        for (int it = 0; it < 8; it++) {
            int idx = tid + it * 128;
            int r = idx >> 4, c = (idx & 15) * 8;
            cp16(ksb + (uint32_t)(r * KH_STRIDE + c) * 2, kptr + (size_t)r * (NKV * HD) + c);
        }
        #pragma unroll
        for (int it = 0; it < 16; it++) {
            int idx = tid + it * 128;
            int r = idx >> 5, c = (idx & 31) * 4;
            cp16(vsb + (uint32_t)(r * VS_STRIDE + c) * 4, vptr + (size_t)r * QKVW + c);
        }
        asm volatile("cp.async.commit_group;");
        asm volatile("cp.async.wait_group 0;");
        __syncthreads();

        float sacc[8][4];
        #pragma unroll
        for (int nt = 0; nt < 8; nt++)
            #pragma unroll
            for (int r = 0; r < 4; r++) sacc[nt][r] = 0.f;

        #pragma unroll
        for (int ks = 0; ks < 8; ks++) {
            int kb = ks * 16 + tig * 2;
            uint32_t ub[8][2];
            #pragma unroll
            for (int nt = 0; nt < 8; nt++) {
                int kr = nt * 8 + g;
                ub[nt][0] = *(const uint32_t*)&Ks[kr * KH_STRIDE + kb];
                ub[nt][1] = *(const uint32_t*)&Ks[kr * KH_STRIDE + kb + 8];
            }
            #pragma unroll
            for (int nt = 0; nt < 8; nt++)
                mma_f16(sacc[nt], qa[ks], ub[nt]);
        }

        bool diag = (kt == ktiles - 1);
        float rmax0 = -1e30f, rmax1 = -1e30f;
        #pragma unroll
        for (int nt = 0; nt < 8; nt++) {
            int c0 = kt * 64 + nt * 8 + tig * 2;
            float s0 = sacc[nt][0] * SCALE;
            float s1 = sacc[nt][1] * SCALE;
            float s2 = sacc[nt][2] * SCALE;
            float s3 = sacc[nt][3] * SCALE;
            if (diag) {
                if (c0 > qr0)     s0 = -1e30f;
                if (c0 + 1 > qr0) s1 = -1e30f;
                if (c0 > qr1)     s2 = -1e30f;
                if (c0 + 1 > qr1) s3 = -1e30f;
            }
            sacc[nt][0] = s0; sacc[nt][1] = s1;
            sacc[nt][2] = s2; sacc[nt][3] = s3;
            rmax0 = fmaxf(rmax0, fmaxf(s0, s1));
            rmax1 = fmaxf(rmax1, fmaxf(s2, s3));
        }
        #pragma unroll
        for (int off = 1; off <= 2; off <<= 1) {
            rmax0 = fmaxf(rmax0, __shfl_xor_sync(0xffffffffu, rmax0, off));
            rmax1 = fmaxf(rmax1, __shfl_xor_sync(0xffffffffu, rmax1, off));
        }
        float mn0 = fmaxf(m0, rmax0);
        float mn1 = fmaxf(m1, rmax1);
        float corr0 = __expf(m0 - mn0);
        float corr1 = __expf(m1 - mn1);
        m0 = mn0; m1 = mn1;

        float psum0 = 0.f, psum1 = 0.f;
        #pragma unroll
        for (int nt = 0; nt < 8; nt++) {
            float p0 = __expf(sacc[nt][0] - mn0);
            float p1 = __expf(sacc[nt][1] - mn0);
            float p2 = __expf(sacc[nt][2] - mn1);
            float p3 = __expf(sacc[nt][3] - mn1);
            psum0 += p0 + p1;
            psum1 += p2 + p3;
            int c = nt * 8 + tig * 2;
            *(float2*)&Ps[(warp * 16 + g) * P_STRIDE + c]     = make_float2(p0, p1);
            *(float2*)&Ps[(warp * 16 + g + 8) * P_STRIDE + c] = make_float2(p2, p3);
        }
        #pragma unroll
        for (int off = 1; off <= 2; off <<= 1) {
            psum0 += __shfl_xor_sync(0xffffffffu, psum0, off);
            psum1 += __shfl_xor_sync(0xffffffffu, psum1, off);
        }
        l0 = l0 * corr0 + psum0;
        l1 = l1 * corr1 + psum1;

        #pragma unroll
        for (int dt = 0; dt < 16; dt++) {
            oacc[dt][0] *= corr0; oacc[dt][1] *= corr0;
            oacc[dt][2] *= corr1; oacc[dt][3] *= corr1;
        }
        __syncwarp();

        #pragma unroll
        for (int ks = 0; ks < 8; ks++) {
            int k8 = ks * 8;
            uint32_t pa[4];
            pa[0] = f2tf32(Ps[(warp * 16 + g) * P_STRIDE + k8 + tig]);
            pa[1] = f2tf32(Ps[(warp * 16 + g + 8) * P_STRIDE + k8 + tig]);
            pa[2] = f2tf32(Ps[(warp * 16 + g) * P_STRIDE + k8 + tig + 4]);
            pa[3] = f2tf32(Ps[(warp * 16 + g + 8) * P_STRIDE + k8 + tig + 4]);
            #pragma unroll
            for (int dt = 0; dt < 16; dt++) {
                uint32_t vb[2];
                vb[0] = f2tf32(Vs[(k8 + tig) * VS_STRIDE + dt * 8 + g]);
                vb[1] = f2tf32(Vs[(k8 + tig + 4) * VS_STRIDE + dt * 8 + g]);
                mma_tf32(oacc[dt], pa, vb);
            }
        }
        __syncthreads();
    }

    float inv0 = 1.f / l0, inv1 = 1.f / l1;
    __half* ob0 = o + ((size_t)(b * SEQ + qr0) * NH + h) * HD;
    __half* ob1 = o + ((size_t)(b * SEQ + qr1) * NH + h) * HD;
    #pragma unroll
    for (int dt = 0; dt < 16; dt++) {
        int d = dt * 8 + tig * 2;
        *(__half2*)(ob0 + d) = __floats2half2_rn(oacc[dt][0] * inv0, oacc[dt][1] * inv0);
        *(__half2*)(ob1 + d) = __floats2half2_rn(oacc[dt][2] * inv1, oacc[dt][3] * inv1);
    }
}

// ---------------- router ----------------
__global__ void zero_cnt_kernel()
{
    if (threadIdx.x < NEXP) g_cnt[threadIdx.x] = 0;
}

__global__ void router_kernel(const float* __restrict__ h2,
                              const float* __restrict__ wr)
{
    int t = blockIdx.x;
    const float* hrow = h2 + (size_t)t * HDIM;
    float l[NEXP];
    #pragma unroll
    for (int e = 0; e < NEXP; e++) l[e] = 0.f;
    for (int kk = threadIdx.x; kk < HDIM; kk += blockDim.x) {
        float hv = hrow[kk];
        const float* wrow = wr + (size_t)kk * NEXP;
        #pragma unroll
        for (int e = 0; e < NEXP; e++) l[e] += hv * wrow[e];
    }
    __shared__ float sums[NEXP];
    if (threadIdx.x < NEXP) sums[threadIdx.x] = 0.f;
    __syncthreads();
    #pragma unroll
    for (int e = 0; e < NEXP; e++) {
        float v = l[e];
        #pragma unroll
        for (int o = 16; o; o >>= 1) v += __shfl_xor_sync(0xffffffffu, v, o);
        if ((threadIdx.x & 31) == 0) atomicAdd(&sums[e], v);
    }
    __syncthreads();
    if (threadIdx.x == 0) {
        int best = 0;
        float bv = sums[0];
        #pragma unroll
        for (int e = 1; e < NEXP; e++)
            if (sums[e] > bv) { bv = sums[e]; best = e; }
        g_tok_expert[t] = best;
        g_tok_scale[t]  = 1.f / (1.f + __expf(-bv));
        g_tok_rank[t]   = atomicAdd(&g_cnt[best], 1);
    }
}

__global__ void offsets_kernel()
{
    if (threadIdx.x == 0) {
        int run = 0;
        for (int e = 0; e < NEXP; e++) { g_off[e] = run; run += g_cnt[e]; }
    }
}

__global__ void slot_kernel()
{
    int t = blockIdx.x * blockDim.x + threadIdx.x;
    if (t < TTOK)
        g_slot_tok[g_off[g_tok_expert[t]] + g_tok_rank[t]] = t;
}

// ---------------- SiLU(g)*u -> fp16 ----------------
__global__ void silu_mul_kernel(const float* __restrict__ gu,
                                __half* __restrict__ out)
{
    int i = blockIdx.x * blockDim.x + threadIdx.x;
    if (i >= TTOK * IDIM) return;
    int row = i / IDIM, col = i - row * IDIM;
    float g = gu[(size_t)row * 2 * IDIM + col];
    float u = gu[(size_t)row * 2 * IDIM + IDIM + col];
    float sg = 1.f / (1.f + __expf(-g));
    out[i] = __float2half(u * g * sg);
}

// ---------------- launch ----------------
extern "C" void kernel_launch(void* const* d_in, const int* in_sizes, int n_in,
                              void* d_out, int out_size)
{
    const float* hidden   = (const float*)d_in[0];
    const float* freqs    = (const float*)d_in[1];
    const float* w_ln1    = (const float*)d_in[2];
    const float* w_qkv    = (const float*)d_in[3];
    const float* w_o      = (const float*)d_in[4];
    const float* w_ln2    = (const float*)d_in[5];
    const float* w_router = (const float*)d_in[6];
    const float* w_gu_e   = (const float*)d_in[7];
    const float* w_down_e = (const float*)d_in[8];
    const float* w_sh_gu  = (const float*)d_in[9];
    const float* w_sh_dn  = (const float*)d_in[10];
    float* out = (float*)d_out;

    float *p_qkv, *p_x2, *p_h2, *p_gus, *p_gur;
    __half *p_h16, *p_q16, *p_k16, *p_o16, *p_h2_16, *p_acs16, *p_acr16;
    __half *p_wqkv16, *p_wo16, *p_wshgu16, *p_wshdn16, *p_wgu16, *p_wdn16;
    cudaGetSymbolAddress((void**)&p_qkv,   g_qkv);
    cudaGetSymbolAddress((void**)&p_x2,    g_x2);
    cudaGetSymbolAddress((void**)&p_h2,    g_h2);
    cudaGetSymbolAddress((void**)&p_gus,   g_gus);
    cudaGetSymbolAddress((void**)&p_gur,   g_gur);
    cudaGetSymbolAddress((void**)&p_h16,   g_h16);
    cudaGetSymbolAddress((void**)&p_q16,   g_q16);
    cudaGetSymbolAddress((void**)&p_k16,   g_k16);
    cudaGetSymbolAddress((void**)&p_o16,   g_o16);
    cudaGetSymbolAddress((void**)&p_h2_16, g_h2_16);
    cudaGetSymbolAddress((void**)&p_acs16, g_acs16);
    cudaGetSymbolAddress((void**)&p_acr16, g_acr16);
    cudaGetSymbolAddress((void**)&p_wqkv16, g_wqkv16);
    cudaGetSymbolAddress((void**)&p_wo16,   g_wo16);
    cudaGetSymbolAddress((void**)&p_wshgu16,g_wshgu16);
    cudaGetSymbolAddress((void**)&p_wshdn16,g_wshdn16);
    cudaGetSymbolAddress((void**)&p_wgu16,  g_wgu16);
    cudaGetSymbolAddress((void**)&p_wdn16,  g_wdn16);

    static int attr_set = 0;
    if (!attr_set) {
        cudaFuncSetAttribute(flash_attn_kernel,
                             cudaFuncAttributeMaxDynamicSharedMemorySize, FA_SMEM);
        cudaFuncSetAttribute(hgemm,
                             cudaFuncAttributeMaxDynamicSharedMemorySize, HG_SMEM);
        attr_set = 1;
    }

    // 0. weight convert fp32 -> fp16 (same layout, fully coalesced)
    {
        size_t n;
        #define CVT(src, dst, nn) do { n = (nn); \
            cvt_kernel<<<(unsigned)((n/8 + 255)/256), 256>>>(src, dst, n); } while (0)
        CVT(w_qkv,    p_wqkv16, (size_t)HDIM * QKVW);
        CVT(w_o,      p_wo16,   (size_t)NH * HD * HDIM);
        CVT(w_sh_gu,  p_wshgu16,(size_t)HDIM * 2 * IDIM);
        CVT(w_sh_dn,  p_wshdn16,(size_t)IDIM * HDIM);
        CVT(w_gu_e,   p_wgu16,  (size_t)NEXP * HDIM * 2 * IDIM);
        CVT(w_down_e, p_wdn16,  (size_t)NEXP * IDIM * HDIM);
        #undef CVT
    }

    // 1. rmsnorm1 -> fp16
    rmsnorm_kernel<<<TTOK, 256>>>(hidden, w_ln1, p_h16, nullptr);
    // 2. qkv = h @ w_qkv
    hgemm<<<dim3(QKVW/128, TTOK/256), 256, HG_SMEM>>>(TTOK, QKVW, HDIM, p_h16, p_wqkv16, 0, p_qkv, nullptr, 0);
    // 3. rope + l2 norm -> fp16 q/k
    rope_l2_kernel<<<dim3(TTOK, 5), 128>>>(p_qkv, freqs, p_q16, p_k16);
    // 4. flash attention -> fp16 O
    flash_attn_kernel<<<dim3(BATCH*NH, SEQ/64), 128, FA_SMEM>>>(p_q16, p_k16, p_qkv, p_o16);
    // 5. x2 = hidden + o @ w_o
    hgemm<<<dim3(HDIM/128, TTOK/256), 256, HG_SMEM>>>(TTOK, HDIM, NH*HD, p_o16, p_wo16, 0, p_x2, hidden, 0);
    // 6. rmsnorm2 -> fp16 + fp32
    rmsnorm_kernel<<<TTOK, 256>>>(p_x2, w_ln2, p_h2_16, p_h2);
    // 7. router (fp32 logits)
    zero_cnt_kernel<<<1, 32>>>();
    router_kernel<<<TTOK, 256>>>(p_h2, w_router);
    offsets_kernel<<<1, 32>>>();
    slot_kernel<<<TTOK/256, 256>>>();
    // 8. shared expert
    hgemm<<<dim3(2*IDIM/128, TTOK/256), 256, HG_SMEM>>>(TTOK, 2*IDIM, HDIM, p_h2_16, p_wshgu16, 0, p_gus, nullptr, 0);
    silu_mul_kernel<<<(TTOK*IDIM + 255)/256, 256>>>(p_gus, p_acs16);
    hgemm<<<dim3(HDIM/128, TTOK/256), 256, HG_SMEM>>>(TTOK, HDIM, IDIM, p_acs16, p_wshdn16, 0, out, p_x2, 0);
    // 9. routed experts (top-1, gathered)
    hgemm<<<dim3(2*IDIM/128, TTOK/256, NEXP), 256, HG_SMEM>>>(TTOK, 2*IDIM, HDIM, p_h2_16, p_wgu16,
                                                              (size_t)HDIM*2*IDIM, p_gur, nullptr, 1);
    silu_mul_kernel<<<(TTOK*IDIM + 255)/256, 256>>>(p_gur, p_acr16);
    hgemm<<<dim3(HDIM/128, TTOK/256, NEXP), 256, HG_SMEM>>>(TTOK, HDIM, IDIM, p_acr16, p_wdn16,
                                                            (size_t)IDIM*HDIM, out, nullptr, 2);
}

// round 17
// speedup vs baseline: 1.3180x; 1.3180x over previous
#include <cuda_runtime.h>
#include <cuda_fp16.h>
#include <stdint.h>
#include <math.h>

// ---------------- problem constants ----------------
#define BATCH 2
#define SEQ   1024
#define HDIM  2048
#define NH    16
#define NKV   4
#define HD    128
#define NEXP  8
#define IDIM  2048
#define TTOK  (BATCH*SEQ)          // 2048 tokens
#define QKVW  ((NH+2*NKV)*HD)      // 3072
#define SCALE 0.08838834764831845f // 128^-0.5
#define EPS_RMS 1e-5f
#define EPS_L2  1e-6f

// ---------------- scratch (device globals; no allocation allowed) ----------
__device__ float  g_qkv [TTOK*QKVW];
__device__ float  g_x2  [TTOK*HDIM];
__device__ float  g_h2  [TTOK*HDIM];

__device__ __half g_h16  [TTOK*HDIM];
__device__ __half g_q16  [TTOK*NH*HD];
__device__ __half g_k16  [TTOK*NKV*HD];
__device__ __half g_o16  [TTOK*NH*HD];
__device__ __half g_h2_16[TTOK*HDIM];
__device__ __half g_acs16[TTOK*IDIM];
__device__ __half g_acr16[TTOK*IDIM];

// fp16 weights, [K][N] layout (gate_up weights column-interleaved)
__device__ __half g_wqkv16 [HDIM*QKVW];
__device__ __half g_wo16   [NH*HD*HDIM];
__device__ __half g_wshgu16[HDIM*2*IDIM];
__device__ __half g_wshdn16[IDIM*HDIM];
__device__ __half g_wgu16  [(size_t)NEXP*HDIM*2*IDIM];
__device__ __half g_wdn16  [(size_t)NEXP*IDIM*HDIM];

__device__ int   g_cnt[NEXP];
__device__ int   g_off[NEXP];
__device__ int   g_tok_expert[TTOK];
__device__ int   g_tok_rank[TTOK];
__device__ float g_tok_scale[TTOK];
__device__ int   g_slot_tok[TTOK];

// ---------------- common PTX helpers ----------------
__device__ __forceinline__ void cp16(uint32_t dst, const void* src) {
    asm volatile("cp.async.ca.shared.global [%0], [%1], 16;" :: "r"(dst), "l"(src));
}
__device__ __forceinline__ uint32_t f2tf32(float f) {
    uint32_t u;
    asm("cvt.rna.tf32.f32 %0, %1;" : "=r"(u) : "f"(f));
    return u;
}
__device__ __forceinline__ void mma_tf32(float* c, const uint32_t* a, const uint32_t* b) {
    asm volatile(
        "mma.sync.aligned.m16n8k8.row.col.f32.tf32.tf32.f32 "
        "{%0,%1,%2,%3}, {%4,%5,%6,%7}, {%8,%9}, {%0,%1,%2,%3};"
        : "+f"(c[0]), "+f"(c[1]), "+f"(c[2]), "+f"(c[3])
        : "r"(a[0]), "r"(a[1]), "r"(a[2]), "r"(a[3]), "r"(b[0]), "r"(b[1]));
}
__device__ __forceinline__ void mma_f16(float* c, const uint32_t* a, const uint32_t* b) {
    asm volatile(
        "mma.sync.aligned.m16n8k16.row.col.f32.f16.f16.f32 "
        "{%0,%1,%2,%3}, {%4,%5,%6,%7}, {%8,%9}, {%0,%1,%2,%3};"
        : "+f"(c[0]), "+f"(c[1]), "+f"(c[2]), "+f"(c[3])
        : "r"(a[0]), "r"(a[1]), "r"(a[2]), "r"(a[3]), "r"(b[0]), "r"(b[1]));
}
__device__ __forceinline__ void ldsm_x4(uint32_t& r0, uint32_t& r1, uint32_t& r2, uint32_t& r3,
                                        uint32_t addr) {
    asm volatile("ldmatrix.sync.aligned.m8n8.x4.shared.b16 {%0,%1,%2,%3}, [%4];"
                 : "=r"(r0), "=r"(r1), "=r"(r2), "=r"(r3) : "r"(addr));
}
__device__ __forceinline__ void ldsm_x4_t(uint32_t& r0, uint32_t& r1, uint32_t& r2, uint32_t& r3,
                                          uint32_t addr) {
    asm volatile("ldmatrix.sync.aligned.m8n8.x4.trans.shared.b16 {%0,%1,%2,%3}, [%4];"
                 : "=r"(r0), "=r"(r1), "=r"(r2), "=r"(r3) : "r"(addr));
}

// ---------------- layout-preserving fp32 -> fp16 convert (R11 proven) ----
__global__ __launch_bounds__(256)
void cvt_kernel(const float* __restrict__ in, __half* __restrict__ out, size_t n)
{
    size_t i = ((size_t)blockIdx.x * 256 + threadIdx.x) * 8;
    if (i >= n) return;
    float4 v0 = *(const float4*)(in + i);
    float4 v1 = *(const float4*)(in + i + 4);
    __half2 h0 = __floats2half2_rn(v0.x, v0.y);
    __half2 h1 = __floats2half2_rn(v0.z, v0.w);
    __half2 h2 = __floats2half2_rn(v1.x, v1.y);
    __half2 h3 = __floats2half2_rn(v1.z, v1.w);
    uint4 pack;
    pack.x = *(uint32_t*)&h0; pack.y = *(uint32_t*)&h1;
    pack.z = *(uint32_t*)&h2; pack.w = *(uint32_t*)&h3;
    *(uint4*)(out + i) = pack;
}

// ---- gate_up convert with column interleave: out[k][2j]=gate_j, [2j+1]=up_j
// in: [K rows][2I] fp32 (gate cols 0..I-1, up cols I..2I-1), per-expert slabs
__global__ __launch_bounds__(256)
void cvt_gu_kernel(const float* __restrict__ in, __half* __restrict__ out,
                   int Krows)
{
    size_t slab = (size_t)blockIdx.z * Krows * 2 * IDIM;
    in  += slab;
    out += slab;
    size_t i = ((size_t)blockIdx.x * 256 + threadIdx.x) * 8;   // output idx
    if (i >= (size_t)Krows * 2 * IDIM) return;
    size_t k = i / (2 * IDIM);
    int c0 = (int)(i - k * 2 * IDIM);   // 8-aligned output col
    int j0 = c0 >> 1;                   // gate/up index
    const float* grow = in + k * 2 * IDIM;
    float4 gv = *(const float4*)(grow + j0);
    float4 uv = *(const float4*)(grow + IDIM + j0);
    __half2 h0 = __floats2half2_rn(gv.x, uv.x);
    __half2 h1 = __floats2half2_rn(gv.y, uv.y);
    __half2 h2 = __floats2half2_rn(gv.z, uv.z);
    __half2 h3 = __floats2half2_rn(gv.w, uv.w);
    uint4 pack;
    pack.x = *(uint32_t*)&h0; pack.y = *(uint32_t*)&h1;
    pack.z = *(uint32_t*)&h2; pack.w = *(uint32_t*)&h3;
    *(uint4*)(out + i) = pack;
}

// ---------------- RMSNorm (fp16 out, optional fp32 out) ----------------
__global__ void rmsnorm_kernel(const float* __restrict__ x,
                               const float* __restrict__ w,
                               __half* __restrict__ out16,
                               float* __restrict__ out32)
{
    int t = blockIdx.x;
    const float* xr = x + (size_t)t * HDIM;
    float ss = 0.f;
    for (int i = threadIdx.x; i < HDIM; i += blockDim.x) {
        float v = xr[i];
        ss += v * v;
    }
    __shared__ float red[8];
    int lane = threadIdx.x & 31, wid = threadIdx.x >> 5;
    #pragma unroll
    for (int o = 16; o; o >>= 1) ss += __shfl_xor_sync(0xffffffffu, ss, o);
    if (lane == 0) red[wid] = ss;
    __syncthreads();
    if (wid == 0) {
        float v = (lane < (blockDim.x >> 5)) ? red[lane] : 0.f;
        #pragma unroll
        for (int o = 16; o; o >>= 1) v += __shfl_xor_sync(0xffffffffu, v, o);
        if (lane == 0) red[0] = v;
    }
    __syncthreads();
    float r = rsqrtf(red[0] / (float)HDIM + EPS_RMS);
    for (int i = threadIdx.x; i < HDIM; i += blockDim.x) {
        float v = xr[i] * r * w[i];
        out16[(size_t)t * HDIM + i] = __float2half(v);
        if (out32) out32[(size_t)t * HDIM + i] = v;
    }
}

// =====================================================================
// fp16 tensor-core GEMM (R11 base): C[M,N] = A[M,K] @ B[K,N]  (+D)
// CTA 128x128, K-tile 32, double-buffered cp.async, 128 threads.
// modes: 0 plain(+D, fp32 out)
//        1 routed gate_up FUSED: gather rows, scale, silu(g)*u -> C16[slot][c/2]
//        2 expert down: slot rows, scatter-accumulate fp32 C[tok]
//        3 shared gate_up FUSED: plain rows, silu(g)*u -> C16[row][c/2]
// =====================================================================
#define AHS 40     // A smem stride (halves)
#define BHS 136    // B smem stride (halves)
#define A_BUF   (128*AHS*2)     // 10240
#define BH_BUF  (32*BHS*2)      // 8704
#define B_OFF   (2*A_BUF)       // 20480
#define HG_SMEM (B_OFF + 2*BH_BUF)  // 37888

__global__ __launch_bounds__(128)
void hgemm(int M, int N, int K,
           const __half* __restrict__ A,
           const __half* __restrict__ B, size_t b_expert_stride,
           float* __restrict__ C,
           __half* __restrict__ C16,
           const float* __restrict__ D,
           int mode)
{
    extern __shared__ char sm[];
    uint32_t smBase = (uint32_t)__cvta_generic_to_shared(sm);

    int crow = blockIdx.y * 128;
    int ccol = blockIdx.x * 128;
    int cnt = M, off = 0;
    if (mode == 1 || mode == 2) {
        int e = blockIdx.z;
        cnt = g_cnt[e];
        off = g_off[e];
        B += (size_t)e * b_expert_stride;
        if (crow >= cnt) return;
    }

    const int tid = threadIdx.x;
    const int warp = tid >> 5, lane = tid & 31;
    const int g = lane >> 2, tig = lane & 3;
    const int wm = (warp >> 1) * 64;
    const int wn = (warp & 1) * 64;

    // ---- A staging: 512 16B chunks -> 4/thread ----
    const __half* a_src[4];
    uint32_t a_off_s[4];
    #pragma unroll
    for (int i = 0; i < 4; i++) {
        int idx = tid + i * 128;
        int r = idx >> 2, c8 = (idx & 3) * 8;
        int gr = crow + r;
        int arow;
        if (mode == 1)      arow = g_slot_tok[off + (gr < cnt ? gr : cnt - 1)];
        else if (mode == 2) arow = off + (gr < cnt ? gr : cnt - 1);
        else                arow = gr;
        a_src[i] = A + (size_t)arow * K + c8;
        a_off_s[i] = (uint32_t)((r * AHS + c8) * 2);
    }
    // ---- B staging: 32 rows x 128 halves = 512 16B chunks -> 4/thread ----
    const __half* b_src[4];
    uint32_t b_off_s[4];
    #pragma unroll
    for (int i = 0; i < 4; i++) {
        int idx = tid + i * 128;
        int r = idx >> 4, c8 = (idx & 15) * 8;
        b_src[i] = B + (size_t)r * N + ccol + c8;
        b_off_s[i] = (uint32_t)((r * BHS + c8) * 2);
    }

    // ldmatrix per-lane offsets
    int lr8 = lane & 7, seg1 = (lane >> 3) & 1, seg2 = lane >> 4;
    uint32_t a_frag = (uint32_t)(((wm + lr8 + seg1 * 8) * AHS + seg2 * 8) * 2);
    int bk = lane & 15, bn = (lane >> 4) * 8;   // trans frag: k row, n half

    float acc[4][8][4];
    #pragma unroll
    for (int mt = 0; mt < 4; mt++)
        #pragma unroll
        for (int nt = 0; nt < 8; nt++)
            #pragma unroll
            for (int r = 0; r < 4; r++) acc[mt][nt][r] = 0.f;

    const int KT = K / 32;

    // prefetch stage 0
    #pragma unroll
    for (int i = 0; i < 4; i++) {
        cp16(smBase + a_off_s[i], a_src[i]);
        cp16(smBase + B_OFF + b_off_s[i], b_src[i]);
    }
    asm volatile("cp.async.commit_group;");

    for (int kt = 0; kt < KT; kt++) {
        int buf = kt & 1;
        if (kt + 1 < KT) {
            int k0 = (kt + 1) * 32;
            int nbuf = buf ^ 1;
            #pragma unroll
            for (int i = 0; i < 4; i++) {
                cp16(smBase + nbuf * A_BUF + a_off_s[i], a_src[i] + k0);
                cp16(smBase + B_OFF + nbuf * BH_BUF + b_off_s[i], b_src[i] + (size_t)k0 * N);
            }
            asm volatile("cp.async.commit_group;");
            asm volatile("cp.async.wait_group 1;");
        } else {
            asm volatile("cp.async.wait_group 0;");
        }
        __syncthreads();

        uint32_t aB  = smBase + buf * A_BUF + a_frag;
        uint32_t bhB = smBase + B_OFF + buf * BH_BUF;

        uint32_t ua[2][4][4], ub[2][8][2];
        #pragma unroll
        for (int ks = 0; ks < 2; ks++) {
            uint32_t ka = aB + ks * 32;
            #pragma unroll
            for (int mt = 0; mt < 4; mt++)
                ldsm_x4(ua[ks][mt][0], ua[ks][mt][1], ua[ks][mt][2], ua[ks][mt][3],
                        ka + mt * (16 * AHS * 2));
            #pragma unroll
            for (int j = 0; j < 4; j++) {
                uint32_t addr = bhB + (uint32_t)(((ks * 16 + bk) * BHS + wn + bn + j * 16) * 2);
                ldsm_x4_t(ub[ks][2*j][0], ub[ks][2*j][1], ub[ks][2*j+1][0], ub[ks][2*j+1][1],
                          addr);
            }
        }
        #pragma unroll
        for (int ks = 0; ks < 2; ks++)
            #pragma unroll
            for (int mt = 0; mt < 4; mt++)
                #pragma unroll
                for (int nt = 0; nt < 8; nt++)
                    mma_f16(acc[mt][nt], ua[ks][mt], ub[ks][nt]);
        __syncthreads();
    }

    // ---------------- epilogue ----------------
    #pragma unroll
    for (int mt = 0; mt < 4; mt++) {
        #pragma unroll
        for (int h = 0; h < 2; h++) {
            int rl = wm + mt * 16 + g + h * 8;
            int gr = crow + rl;
            if (mode == 0) {
                size_t rbase = (size_t)gr * N;
                #pragma unroll
                for (int nt = 0; nt < 8; nt++) {
                    int c = ccol + wn + nt * 8 + tig * 2;
                    float v0 = acc[mt][nt][h * 2 + 0];
                    float v1 = acc[mt][nt][h * 2 + 1];
                    if (D) {
                        float2 dv = *(const float2*)(D + rbase + c);
                        v0 += dv.x; v1 += dv.y;
                    }
                    *(float2*)(C + rbase + c) = make_float2(v0, v1);
                }
            } else if (mode == 1) {
                if (gr < cnt) {
                    int slot = off + gr;
                    float s = g_tok_scale[g_slot_tok[slot]];
                    size_t rbase = (size_t)slot * (N / 2);
                    #pragma unroll
                    for (int nt = 0; nt < 8; nt++) {
                        int c = ccol + wn + nt * 8 + tig * 2;
                        float gg = s * acc[mt][nt][h * 2 + 0];   // gate
                        float uu = s * acc[mt][nt][h * 2 + 1];   // up
                        float act = gg / (1.f + __expf(-gg)) * uu;
                        C16[rbase + (c >> 1)] = __float2half(act);
                    }
                }
            } else if (mode == 2) {
                if (gr < cnt) {
                    int tok = g_slot_tok[off + gr];
                    size_t rbase = (size_t)tok * N;
                    #pragma unroll
                    for (int nt = 0; nt < 8; nt++) {
                        int c = ccol + wn + nt * 8 + tig * 2;
                        float2* cp = (float2*)(C + rbase + c);
                        float2 cv = *cp;
                        cv.x += acc[mt][nt][h * 2 + 0];
                        cv.y += acc[mt][nt][h * 2 + 1];
                        *cp = cv;
                    }
                }
            } else { // mode 3: shared gate_up fused
                size_t rbase = (size_t)gr * (N / 2);
                #pragma unroll
                for (int nt = 0; nt < 8; nt++) {
                    int c = ccol + wn + nt * 8 + tig * 2;
                    float gg = acc[mt][nt][h * 2 + 0];
                    float uu = acc[mt][nt][h * 2 + 1];
                    float act = gg / (1.f + __expf(-gg)) * uu;
                    C16[rbase + (c >> 1)] = __float2half(act);
                }
            }
        }
    }
}

// ---------------- RoPE + L2-norm for q & k -> fp16 ----------------
__global__ void rope_l2_kernel(const float* __restrict__ qkv,
                               const float* __restrict__ freqs,
                               __half* __restrict__ qout,
                               __half* __restrict__ kout)
{
    int t = blockIdx.x;
    int lane = threadIdx.x & 31, w = threadIdx.x >> 5;
    int hh = blockIdx.y * 4 + w;
    int s = t & (SEQ - 1);

    const float* src;
    __half* dst;
    if (hh < NH) {
        src = qkv + (size_t)t * QKVW + hh * HD;
        dst = qout + (size_t)t * NH * HD + hh * HD;
    } else {
        int kv = hh - NH;
        src = qkv + (size_t)t * QKVW + NH * HD + kv * HD;
        dst = kout + (size_t)t * NKV * HD + kv * HD;
    }
    float4 xv = *(const float4*)(src + lane * 4);
    float4 fv = *(const float4*)(freqs + (size_t)s * HD + lane * 4);
    float o0 = xv.x * fv.x - xv.y * fv.y;
    float o1 = xv.x * fv.y + xv.y * fv.x;
    float o2 = xv.z * fv.z - xv.w * fv.w;
    float o3 = xv.z * fv.w + xv.w * fv.z;
    float ss = o0*o0 + o1*o1 + o2*o2 + o3*o3;
    #pragma unroll
    for (int o = 16; o; o >>= 1) ss += __shfl_xor_sync(0xffffffffu, ss, o);
    float r = rsqrtf(ss / (float)HD + EPS_L2);
    __half2 p0 = __floats2half2_rn(o0 * r, o1 * r);
    __half2 p1 = __floats2half2_rn(o2 * r, o3 * r);
    *(__half2*)(dst + lane * 4)     = p0;
    *(__half2*)(dst + lane * 4 + 2) = p1;
}

// =====================================================================
// flash attention (R11 proven): fp16 S-path, tf32 P@V, 64 q rows/block,
// longest q-tiles first.
// =====================================================================
#define KH_STRIDE 136   // halves
#define VS_STRIDE 136   // floats
#define P_STRIDE  68    // floats
#define FA_SMEM   (64*KH_STRIDE*2 + 64*VS_STRIDE*4 + 64*P_STRIDE*4)

__global__ __launch_bounds__(128)
void flash_attn_kernel(const __half* __restrict__ q,
                       const __half* __restrict__ k,
                       const float* __restrict__ qkv,
                       __half* __restrict__ o)
{
    extern __shared__ char fsm[];
    __half* Ks = (__half*)fsm;                         // [64][KH_STRIDE]
    float*  Vs = (float*)(fsm + 64 * KH_STRIDE * 2);   // [64][VS_STRIDE]
    float*  Ps = Vs + 64 * VS_STRIDE;                  // [64][P_STRIDE]

    int bh = blockIdx.x;
    int b = bh >> 4, h = bh & 15;
    int kvh = h >> 2;
    int qt = gridDim.y - 1 - blockIdx.y;   // longest first
    int q0 = qt * 64;

    int tid = threadIdx.x, warp = tid >> 5, lane = tid & 31;
    int g = lane >> 2, tig = lane & 3;

    int qr0 = q0 + warp * 16 + g;
    int qr1 = qr0 + 8;
    const __half* qb0 = q + ((size_t)(b * SEQ + qr0) * NH + h) * HD;
    const __half* qb1 = q + ((size_t)(b * SEQ + qr1) * NH + h) * HD;
    uint32_t qa[8][4];
    #pragma unroll
    for (int ks = 0; ks < 8; ks++) {
        int c = ks * 16 + tig * 2;
        qa[ks][0] = *(const uint32_t*)&qb0[c];
        qa[ks][1] = *(const uint32_t*)&qb1[c];
        qa[ks][2] = *(const uint32_t*)&qb0[c + 8];
        qa[ks][3] = *(const uint32_t*)&qb1[c + 8];
    }

    float oacc[16][4];
    #pragma unroll
    for (int dt = 0; dt < 16; dt++)
        #pragma unroll
        for (int r = 0; r < 4; r++) oacc[dt][r] = 0.f;
    float m0 = -1e30f, m1 = -1e30f, l0 = 0.f, l1 = 0.f;

    uint32_t ksb = (uint32_t)__cvta_generic_to_shared(Ks);
    uint32_t vsb = (uint32_t)__cvta_generic_to_shared(Vs);

    const int ktiles = qt + 1;
    for (int kt = 0; kt < ktiles; kt++) {
        const __half* kptr = k + ((size_t)(b * SEQ + kt * 64) * NKV + kvh) * HD;
        const float*  vptr = qkv + (size_t)(b * SEQ + kt * 64) * QKVW + (NH + NKV) * HD + kvh * HD;
        #pragma unroll
        for (int it = 0; it < 8; it++) {
            int idx = tid + it * 128;
            int r = idx >> 4, c = (idx & 15) * 8;
            cp16(ksb + (uint32_t)(r * KH_STRIDE + c) * 2, kptr + (size_t)r * (NKV * HD) + c);
        }
        #pragma unroll
        for (int it = 0; it < 16; it++) {
            int idx = tid + it * 128;
            int r = idx >> 5, c = (idx & 31) * 4;
            cp16(vsb + (uint32_t)(r * VS_STRIDE + c) * 4, vptr + (size_t)r * QKVW + c);
        }
        asm volatile("cp.async.commit_group;");
        asm volatile("cp.async.wait_group 0;");
        __syncthreads();

        float sacc[8][4];
        #pragma unroll
        for (int nt = 0; nt < 8; nt++)
            #pragma unroll
            for (int r = 0; r < 4; r++) sacc[nt][r] = 0.f;

        #pragma unroll
        for (int ks = 0; ks < 8; ks++) {
            int kb = ks * 16 + tig * 2;
            uint32_t ub[8][2];
            #pragma unroll
            for (int nt = 0; nt < 8; nt++) {
                int kr = nt * 8 + g;
                ub[nt][0] = *(const uint32_t*)&Ks[kr * KH_STRIDE + kb];
                ub[nt][1] = *(const uint32_t*)&Ks[kr * KH_STRIDE + kb + 8];
            }
            #pragma unroll
            for (int nt = 0; nt < 8; nt++)
                mma_f16(sacc[nt], qa[ks], ub[nt]);
        }

        bool diag = (kt == ktiles - 1);
        float rmax0 = -1e30f, rmax1 = -1e30f;
        #pragma unroll
        for (int nt = 0; nt < 8; nt++) {
            int c0 = kt * 64 + nt * 8 + tig * 2;
            float s0 = sacc[nt][0] * SCALE;
            float s1 = sacc[nt][1] * SCALE;
            float s2 = sacc[nt][2] * SCALE;
            float s3 = sacc[nt][3] * SCALE;
            if (diag) {
                if (c0 > qr0)     s0 = -1e30f;
                if (c0 + 1 > qr0) s1 = -1e30f;
                if (c0 > qr1)     s2 = -1e30f;
                if (c0 + 1 > qr1) s3 = -1e30f;
            }
            sacc[nt][0] = s0; sacc[nt][1] = s1;
            sacc[nt][2] = s2; sacc[nt][3] = s3;
            rmax0 = fmaxf(rmax0, fmaxf(s0, s1));
            rmax1 = fmaxf(rmax1, fmaxf(s2, s3));
        }
        #pragma unroll
        for (int off = 1; off <= 2; off <<= 1) {
            rmax0 = fmaxf(rmax0, __shfl_xor_sync(0xffffffffu, rmax0, off));
            rmax1 = fmaxf(rmax1, __shfl_xor_sync(0xffffffffu, rmax1, off));
        }
        float mn0 = fmaxf(m0, rmax0);
        float mn1 = fmaxf(m1, rmax1);
        float corr0 = __expf(m0 - mn0);
        float corr1 = __expf(m1 - mn1);
        m0 = mn0; m1 = mn1;

        float psum0 = 0.f, psum1 = 0.f;
        #pragma unroll
        for (int nt = 0; nt < 8; nt++) {
            float p0 = __expf(sacc[nt][0] - mn0);
            float p1 = __expf(sacc[nt][1] - mn0);
            float p2 = __expf(sacc[nt][2] - mn1);
            float p3 = __expf(sacc[nt][3] - mn1);
            psum0 += p0 + p1;
            psum1 += p2 + p3;
            int c = nt * 8 + tig * 2;
            *(float2*)&Ps[(warp * 16 + g) * P_STRIDE + c]     = make_float2(p0, p1);
            *(float2*)&Ps[(warp * 16 + g + 8) * P_STRIDE + c] = make_float2(p2, p3);
        }
        #pragma unroll
        for (int off = 1; off <= 2; off <<= 1) {
            psum0 += __shfl_xor_sync(0xffffffffu, psum0, off);
            psum1 += __shfl_xor_sync(0xffffffffu, psum1, off);
        }
        l0 = l0 * corr0 + psum0;
        l1 = l1 * corr1 + psum1;

        #pragma unroll
        for (int dt = 0; dt < 16; dt++) {
            oacc[dt][0] *= corr0; oacc[dt][1] *= corr0;
            oacc[dt][2] *= corr1; oacc[dt][3] *= corr1;
        }
        __syncwarp();

        #pragma unroll
        for (int ks = 0; ks < 8; ks++) {
            int k8 = ks * 8;
            uint32_t pa[4];
            pa[0] = f2tf32(Ps[(warp * 16 + g) * P_STRIDE + k8 + tig]);
            pa[1] = f2tf32(Ps[(warp * 16 + g + 8) * P_STRIDE + k8 + tig]);
            pa[2] = f2tf32(Ps[(warp * 16 + g) * P_STRIDE + k8 + tig + 4]);
            pa[3] = f2tf32(Ps[(warp * 16 + g + 8) * P_STRIDE + k8 + tig + 4]);
            #pragma unroll
            for (int dt = 0; dt < 16; dt++) {
                uint32_t vb[2];
                vb[0] = f2tf32(Vs[(k8 + tig) * VS_STRIDE + dt * 8 + g]);
                vb[1] = f2tf32(Vs[(k8 + tig + 4) * VS_STRIDE + dt * 8 + g]);
                mma_tf32(oacc[dt], pa, vb);
            }
        }
        __syncthreads();
    }

    float inv0 = 1.f / l0, inv1 = 1.f / l1;
    __half* ob0 = o + ((size_t)(b * SEQ + qr0) * NH + h) * HD;
    __half* ob1 = o + ((size_t)(b * SEQ + qr1) * NH + h) * HD;
    #pragma unroll
    for (int dt = 0; dt < 16; dt++) {
        int d = dt * 8 + tig * 2;
        *(__half2*)(ob0 + d) = __floats2half2_rn(oacc[dt][0] * inv0, oacc[dt][1] * inv0);
        *(__half2*)(ob1 + d) = __floats2half2_rn(oacc[dt][2] * inv1, oacc[dt][3] * inv1);
    }
}

// ---------------- router ----------------
__global__ void zero_cnt_kernel()
{
    if (threadIdx.x < NEXP) g_cnt[threadIdx.x] = 0;
}

__global__ void router_kernel(const float* __restrict__ h2,
                              const float* __restrict__ wr)
{
    int t = blockIdx.x;
    const float* hrow = h2 + (size_t)t * HDIM;
    float l[NEXP];
    #pragma unroll
    for (int e = 0; e < NEXP; e++) l[e] = 0.f;
    for (int kk = threadIdx.x; kk < HDIM; kk += blockDim.x) {
        float hv = hrow[kk];
        const float* wrow = wr + (size_t)kk * NEXP;
        #pragma unroll
        for (int e = 0; e < NEXP; e++) l[e] += hv * wrow[e];
    }
    __shared__ float sums[NEXP];
    if (threadIdx.x < NEXP) sums[threadIdx.x] = 0.f;
    __syncthreads();
    #pragma unroll
    for (int e = 0; e < NEXP; e++) {
        float v = l[e];
        #pragma unroll
        for (int o = 16; o; o >>= 1) v += __shfl_xor_sync(0xffffffffu, v, o);
        if ((threadIdx.x & 31) == 0) atomicAdd(&sums[e], v);
    }
    __syncthreads();
    if (threadIdx.x == 0) {
        int best = 0;
        float bv = sums[0];
        #pragma unroll
        for (int e = 1; e < NEXP; e++)
            if (sums[e] > bv) { bv = sums[e]; best = e; }
        g_tok_expert[t] = best;
        g_tok_scale[t]  = 1.f / (1.f + __expf(-bv));
        g_tok_rank[t]   = atomicAdd(&g_cnt[best], 1);
    }
}

__global__ void offsets_kernel()
{
    if (threadIdx.x == 0) {
        int run = 0;
        for (int e = 0; e < NEXP; e++) { g_off[e] = run; run += g_cnt[e]; }
    }
}

__global__ void slot_kernel()
{
    int t = blockIdx.x * blockDim.x + threadIdx.x;
    if (t < TTOK)
        g_slot_tok[g_off[g_tok_expert[t]] + g_tok_rank[t]] = t;
}

// ---------------- launch ----------------
extern "C" void kernel_launch(void* const* d_in, const int* in_sizes, int n_in,
                              void* d_out, int out_size)
{
    const float* hidden   = (const float*)d_in[0];
    const float* freqs    = (const float*)d_in[1];
    const float* w_ln1    = (const float*)d_in[2];
    const float* w_qkv    = (const float*)d_in[3];
    const float* w_o      = (const float*)d_in[4];
    const float* w_ln2    = (const float*)d_in[5];
    const float* w_router = (const float*)d_in[6];
    const float* w_gu_e   = (const float*)d_in[7];
    const float* w_down_e = (const float*)d_in[8];
    const float* w_sh_gu  = (const float*)d_in[9];
    const float* w_sh_dn  = (const float*)d_in[10];
    float* out = (float*)d_out;

    float *p_qkv, *p_x2, *p_h2;
    __half *p_h16, *p_q16, *p_k16, *p_o16, *p_h2_16, *p_acs16, *p_acr16;
    __half *p_wqkv16, *p_wo16, *p_wshgu16, *p_wshdn16, *p_wgu16, *p_wdn16;
    cudaGetSymbolAddress((void**)&p_qkv,   g_qkv);
    cudaGetSymbolAddress((void**)&p_x2,    g_x2);
    cudaGetSymbolAddress((void**)&p_h2,    g_h2);
    cudaGetSymbolAddress((void**)&p_h16,   g_h16);
    cudaGetSymbolAddress((void**)&p_q16,   g_q16);
    cudaGetSymbolAddress((void**)&p_k16,   g_k16);
    cudaGetSymbolAddress((void**)&p_o16,   g_o16);
    cudaGetSymbolAddress((void**)&p_h2_16, g_h2_16);
    cudaGetSymbolAddress((void**)&p_acs16, g_acs16);
    cudaGetSymbolAddress((void**)&p_acr16, g_acr16);
    cudaGetSymbolAddress((void**)&p_wqkv16, g_wqkv16);
    cudaGetSymbolAddress((void**)&p_wo16,   g_wo16);
    cudaGetSymbolAddress((void**)&p_wshgu16,g_wshgu16);
    cudaGetSymbolAddress((void**)&p_wshdn16,g_wshdn16);
    cudaGetSymbolAddress((void**)&p_wgu16,  g_wgu16);
    cudaGetSymbolAddress((void**)&p_wdn16,  g_wdn16);

    static int attr_set = 0;
    if (!attr_set) {
        cudaFuncSetAttribute(flash_attn_kernel,
                             cudaFuncAttributeMaxDynamicSharedMemorySize, FA_SMEM);
        cudaFuncSetAttribute(hgemm,
                             cudaFuncAttributeMaxDynamicSharedMemorySize, HG_SMEM);
        attr_set = 1;
    }

    // 0. weight convert fp32 -> fp16; gate_up weights column-interleaved
    {
        size_t n;
        #define CVT(src, dst, nn) do { n = (nn); \
            cvt_kernel<<<(unsigned)((n/8 + 255)/256), 256>>>(src, dst, n); } while (0)
        CVT(w_qkv,    p_wqkv16, (size_t)HDIM * QKVW);
        CVT(w_o,      p_wo16,   (size_t)NH * HD * HDIM);
        CVT(w_sh_dn,  p_wshdn16,(size_t)IDIM * HDIM);
        CVT(w_down_e, p_wdn16,  (size_t)NEXP * IDIM * HDIM);
        #undef CVT
        unsigned nb = (unsigned)(((size_t)HDIM * 2 * IDIM / 8 + 255) / 256);
        cvt_gu_kernel<<<dim3(nb, 1, 1), 256>>>(w_sh_gu, p_wshgu16, HDIM);
        cvt_gu_kernel<<<dim3(nb, 1, NEXP), 256>>>(w_gu_e, p_wgu16, HDIM);
    }

    // 1. rmsnorm1 -> fp16
    rmsnorm_kernel<<<TTOK, 256>>>(hidden, w_ln1, p_h16, nullptr);
    // 2. qkv = h @ w_qkv
    hgemm<<<dim3(QKVW/128, TTOK/128), 128, HG_SMEM>>>(TTOK, QKVW, HDIM, p_h16, p_wqkv16, 0,
                                                      p_qkv, nullptr, nullptr, 0);
    // 3. rope + l2 norm -> fp16 q/k
    rope_l2_kernel<<<dim3(TTOK, 5), 128>>>(p_qkv, freqs, p_q16, p_k16);
    // 4. flash attention -> fp16 O
    flash_attn_kernel<<<dim3(BATCH*NH, SEQ/64), 128, FA_SMEM>>>(p_q16, p_k16, p_qkv, p_o16);
    // 5. x2 = hidden + o @ w_o
    hgemm<<<dim3(HDIM/128, TTOK/128), 128, HG_SMEM>>>(TTOK, HDIM, NH*HD, p_o16, p_wo16, 0,
                                                      p_x2, nullptr, hidden, 0);
    // 6. rmsnorm2 -> fp16 + fp32
    rmsnorm_kernel<<<TTOK, 256>>>(p_x2, w_ln2, p_h2_16, p_h2);
    // 7. router (fp32 logits)
    zero_cnt_kernel<<<1, 32>>>();
    router_kernel<<<TTOK, 256>>>(p_h2, w_router);
    offsets_kernel<<<1, 32>>>();
    slot_kernel<<<TTOK/256, 256>>>();
    // 8. shared expert: fused gate_up+silu -> acs16, then down-proj
    hgemm<<<dim3(2*IDIM/128, TTOK/128), 128, HG_SMEM>>>(TTOK, 2*IDIM, HDIM, p_h2_16, p_wshgu16, 0,
                                                        nullptr, p_acs16, nullptr, 3);
    hgemm<<<dim3(HDIM/128, TTOK/128), 128, HG_SMEM>>>(TTOK, HDIM, IDIM, p_acs16, p_wshdn16, 0,
                                                      out, nullptr, p_x2, 0);
    // 9. routed experts: fused gather+scale+gate_up+silu -> acr16, then scatter down
    hgemm<<<dim3(2*IDIM/128, TTOK/128, NEXP), 128, HG_SMEM>>>(TTOK, 2*IDIM, HDIM, p_h2_16, p_wgu16,
                                                              (size_t)HDIM*2*IDIM,
                                                              nullptr, p_acr16, nullptr, 1);
    hgemm<<<dim3(HDIM/128, TTOK/128, NEXP), 128, HG_SMEM>>>(TTOK, HDIM, IDIM, p_acr16, p_wdn16,
                                                            (size_t)IDIM*HDIM,
                                                            out, nullptr, nullptr, 2);
}